// round 1
// baseline (speedup 1.0000x reference)
#include <cuda_runtime.h>
#include <cuda_bf16.h>
#include <math.h>

// Problem constants
#define B_  16384
#define F_  32
#define D_  64
#define IN_ 2048   // F_*D_
#define EPS_ 1e-5f

// ---------------------------------------------------------------------------
// Scratch: mask[B,F] produced by k1, consumed by k2. (No device mallocs allowed.)
// ---------------------------------------------------------------------------
__device__ float g_mask_buf[(size_t)B_ * F_];

// ===========================================================================
// Kernel 1: mask branch.
//   C[B,96] = flat[B,2048] @ [mw1 | mlw]   (h0 in cols 0..63, res in cols 64..95)
//   then per-row: h = elu(h0+mb1)@mw2+mb2
//                 pre = sigmoid(h@mgw+mgb)*(h@mlw2+mlb2) + (res+mlb)
//                 mask = softmax(layernorm(pre, mgamma, mbeta))
// Tiling: BM=128, BN=96, BK=32, 256 threads, 8x6 register tile per thread.
// ===========================================================================
#define BM 128
#define BN 96
#define BK 32
#define AS_STRIDE 36   // BK + 4 pad, keeps 16B alignment for float4 STS
#define BS_STRIDE 100  // BN + 4 pad
#define CS_STRIDE 97   // BN + 1 pad

// smem layout (floats):
//   As   [BM][AS_STRIDE]        = 4608
//   Bs   [BK][BS_STRIDE]        = 3200
//   Cs   [BM][CS_STRIDE]        = 12416
//   mw2s [64*32]                = 2048
//   mgws [32*32]                = 1024
//   mlw2s[32*32]                = 1024
//   biases (mb1 64, mb2/mgb/mlb2/mlb/mgamma/mbeta 32 each) = 256
// total = 24576 floats = 96 KB
#define K1_SMEM_FLOATS 24576

__global__ __launch_bounds__(256, 1)
void k1_mask_kernel(const float* __restrict__ x,
                    const float* __restrict__ mw1, const float* __restrict__ mb1,
                    const float* __restrict__ mw2, const float* __restrict__ mb2,
                    const float* __restrict__ mlw, const float* __restrict__ mlb,
                    const float* __restrict__ mgw, const float* __restrict__ mgb,
                    const float* __restrict__ mlw2, const float* __restrict__ mlb2,
                    const float* __restrict__ mgamma, const float* __restrict__ mbeta,
                    float* __restrict__ gmask, float* __restrict__ out_mask)
{
    extern __shared__ float sm[];
    float* As    = sm;                       // [BM][AS_STRIDE]
    float* Bs    = As  + BM * AS_STRIDE;     // [BK][BS_STRIDE]
    float* Cs    = Bs  + BK * BS_STRIDE;     // [BM][CS_STRIDE]
    float* mw2s  = Cs  + BM * CS_STRIDE;     // [64][32]
    float* mgws  = mw2s + 64 * 32;           // [32][32]
    float* mlw2s = mgws + 32 * 32;           // [32][32]
    float* mb1s  = mlw2s + 32 * 32;          // 64
    float* mb2s  = mb1s + 64;                // 32
    float* mgbs  = mb2s + 32;
    float* mlb2s = mgbs + 32;
    float* mlbs  = mlb2s + 32;
    float* mgammas = mlbs + 32;
    float* mbetas  = mgammas + 32;

    const int tid = threadIdx.x;
    const int ty = tid / 16;       // 0..15  -> rows ty*8..ty*8+7
    const int tx = tid % 16;       // 0..15  -> cols tx*6..tx*6+5
    const int m0 = blockIdx.x * BM;

    // stage small epilogue weights once
    for (int i = tid; i < 64 * 32; i += 256) mw2s[i] = mw2[i];
    for (int i = tid; i < 32 * 32; i += 256) { mgws[i] = mgw[i]; mlw2s[i] = mlw2[i]; }
    if (tid < 64) mb1s[tid] = mb1[tid];
    if (tid < 32) {
        mb2s[tid]  = mb2[tid];  mgbs[tid] = mgb[tid];  mlb2s[tid] = mlb2[tid];
        mlbs[tid]  = mlb[tid];  mgammas[tid] = mgamma[tid]; mbetas[tid] = mbeta[tid];
    }

    float c[8][6];
#pragma unroll
    for (int i = 0; i < 8; i++)
#pragma unroll
        for (int j = 0; j < 6; j++) c[i][j] = 0.f;

    const int ar  = tid / 8;        // 0..31
    const int ac  = (tid % 8) * 4;  // 0..28
    const int br  = tid / 8;        // 0..31
    const int bc8 = tid % 8;

    for (int k0 = 0; k0 < IN_; k0 += BK) {
        __syncthreads();
        // A tile: 128 x 32
#pragma unroll
        for (int p = 0; p < 4; p++) {
            int m = ar + 32 * p;
            float4 v = *(const float4*)&x[(size_t)(m0 + m) * IN_ + k0 + ac];
            *(float4*)&As[m * AS_STRIDE + ac] = v;
        }
        // B tile: 32 x 96  (mw1 cols 0..63, mlw cols 64..95)
#pragma unroll
        for (int q = 0; q < 3; q++) {
            int c4  = bc8 * 3 + q;    // 0..23
            int col = c4 * 4;
            float4 v;
            if (col < 64) v = *(const float4*)&mw1[(size_t)(k0 + br) * 64 + col];
            else          v = *(const float4*)&mlw[(size_t)(k0 + br) * 32 + (col - 64)];
            *(float4*)&Bs[br * BS_STRIDE + col] = v;
        }
        __syncthreads();

#pragma unroll
        for (int k = 0; k < BK; k++) {
            float a[8], b[6];
#pragma unroll
            for (int i = 0; i < 8; i++) a[i] = As[(ty * 8 + i) * AS_STRIDE + k];
#pragma unroll
            for (int j = 0; j < 3; j++) {
                float2 bv = *(const float2*)&Bs[k * BS_STRIDE + tx * 6 + 2 * j];
                b[2 * j] = bv.x; b[2 * j + 1] = bv.y;
            }
#pragma unroll
            for (int i = 0; i < 8; i++)
#pragma unroll
                for (int j = 0; j < 6; j++) c[i][j] = fmaf(a[i], b[j], c[i][j]);
        }
    }
    __syncthreads();
    // stage C
#pragma unroll
    for (int i = 0; i < 8; i++)
#pragma unroll
        for (int j = 0; j < 6; j++)
            Cs[(ty * 8 + i) * CS_STRIDE + tx * 6 + j] = c[i][j];
    __syncthreads();

    // per-row epilogue: threads 0..127 own row tid
    if (tid < BM) {
        const int base = tid * CS_STRIDE;
        const size_t gr = (size_t)(m0 + tid);

        // ELU(h0 + mb1) in place
#pragma unroll 4
        for (int e = 0; e < 64; e++) {
            float v = Cs[base + e] + mb1s[e];
            Cs[base + e] = v > 0.f ? v : expm1f(v);
        }
        // h = eh @ mw2 + mb2
        float h[32];
#pragma unroll
        for (int j = 0; j < 32; j++) h[j] = mb2s[j];
#pragma unroll 4
        for (int e = 0; e < 64; e++) {
            float ev = Cs[base + e];
#pragma unroll
            for (int j = 0; j < 32; j++) h[j] = fmaf(ev, mw2s[e * 32 + j], h[j]);
        }
        // stash h back into Cs cols 0..31 so loops below can stay rolled
#pragma unroll
        for (int j = 0; j < 32; j++) Cs[base + j] = h[j];

        float g[32], l[32];
#pragma unroll
        for (int j = 0; j < 32; j++) { g[j] = mgbs[j]; l[j] = mlb2s[j]; }
#pragma unroll 2
        for (int i = 0; i < 32; i++) {
            float hv = Cs[base + i];
#pragma unroll
            for (int j = 0; j < 32; j++) {
                g[j] = fmaf(hv, mgws[i * 32 + j], g[j]);
                l[j] = fmaf(hv, mlw2s[i * 32 + j], l[j]);
            }
        }
        float pre[32];
#pragma unroll
        for (int j = 0; j < 32; j++) {
            float sig = 1.f / (1.f + expf(-g[j]));
            pre[j] = fmaf(sig, l[j], Cs[base + 64 + j] + mlbs[j]);
        }
        // layernorm over 32
        float mean = 0.f;
#pragma unroll
        for (int j = 0; j < 32; j++) mean += pre[j];
        mean *= (1.f / 32.f);
        float var = 0.f;
#pragma unroll
        for (int j = 0; j < 32; j++) { float d = pre[j] - mean; var = fmaf(d, d, var); }
        var *= (1.f / 32.f);
        float inv = rsqrtf(var + EPS_);
        float mx = -3.4e38f;
#pragma unroll
        for (int j = 0; j < 32; j++) {
            pre[j] = fmaf((pre[j] - mean) * inv, mgammas[j], mbetas[j]);
            mx = fmaxf(mx, pre[j]);
        }
        // softmax
        float ssum = 0.f;
#pragma unroll
        for (int j = 0; j < 32; j++) { pre[j] = expf(pre[j] - mx); ssum += pre[j]; }
        float rinv = 1.f / ssum;
#pragma unroll
        for (int j = 0; j < 32; j++) {
            float mv = pre[j] * rinv;
            g_mask_buf[gr * 32 + j] = mv;
            if (out_mask) out_mask[gr * 32 + j] = mv;
        }
    }
}

// ===========================================================================
// Kernel 2: per-feature GRNs + mask-weighted reduction.
// 128 rows per CTA, 1 thread per row. Per feature f: stage w1/w2/gw/lw (+bias,
// gamma/beta) in smem; GEMV chain with 64-reg accumulators; hh staged in a
// per-thread smem column (no cross-thread hazards); layernorm; accumulate
// mask[b,f]*vecs into smem accumulator; coalesced float4 store at the end.
// ===========================================================================
#define K2_ROWS 128
#define K2_THREADS 128
#define XS_STRIDE 132   // K2_ROWS + 4

// smem floats: 4*4096 (w) + 6*64 (vec) + 3*64*XS_STRIDE (xs, hh, acc)
#define K2_SMEM_FLOATS (4*4096 + 6*64 + 3*64*XS_STRIDE)

__global__ __launch_bounds__(K2_THREADS, 1)
void k2_grn_kernel(const float* __restrict__ x,
                   const float* __restrict__ w1, const float* __restrict__ b1,
                   const float* __restrict__ w2, const float* __restrict__ b2,
                   const float* __restrict__ gw, const float* __restrict__ gb,
                   const float* __restrict__ lw, const float* __restrict__ lb,
                   const float* __restrict__ gamma, const float* __restrict__ beta,
                   float* __restrict__ out)
{
    extern __shared__ float sm[];
    float* w1s = sm;               // [64][64] row-major (d,e)
    float* w2s = w1s + 4096;
    float* gws = w2s + 4096;
    float* lws = gws + 4096;
    float* b1s = lws + 4096;       // 64 each
    float* b2s = b1s + 64;
    float* gbs = b2s + 64;
    float* lbs = gbs + 64;
    float* gms = lbs + 64;         // gamma
    float* bts = gms + 64;         // beta
    float* xs  = bts + 64;         // [64][XS_STRIDE]  xs[d*XS_STRIDE + r]
    float* hhs = xs  + 64 * XS_STRIDE;
    float* accs = hhs + 64 * XS_STRIDE;

    const int tid = threadIdx.x;
    const int r   = tid;                       // row within block
    const int r0  = blockIdx.x * K2_ROWS;
    const size_t gr = (size_t)(r0 + r);

    // zero out-accumulator (own column)
#pragma unroll
    for (int e = 0; e < 64; e++) accs[e * XS_STRIDE + r] = 0.f;

    for (int f = 0; f < F_; f++) {
        __syncthreads();   // protect smem reuse across features
        // ---- stage weights for feature f ----
        {
            const size_t wo = (size_t)f * 4096;
#pragma unroll
            for (int q = 0; q < 8; q++) {
                int idx = tid + K2_THREADS * q;   // float4 index 0..1023
                *(float4*)(w1s + 4 * idx) = *(const float4*)(w1 + wo + 4 * idx);
                *(float4*)(w2s + 4 * idx) = *(const float4*)(w2 + wo + 4 * idx);
                *(float4*)(gws + 4 * idx) = *(const float4*)(gw + wo + 4 * idx);
                *(float4*)(lws + 4 * idx) = *(const float4*)(lw + wo + 4 * idx);
            }
            if (tid < 64) {
                b1s[tid] = b1[f * 64 + tid];  b2s[tid] = b2[f * 64 + tid];
                gbs[tid] = gb[f * 64 + tid];  lbs[tid] = lb[f * 64 + tid];
                gms[tid] = gamma[f * 64 + tid]; bts[tid] = beta[f * 64 + tid];
            }
        }
        // ---- stage x[r0:r0+128, f, :] transposed: xs[d][r] ----
#pragma unroll
        for (int i = 0; i < 16; i++) {
            int j   = tid + K2_THREADS * i;  // float4 index 0..2047
            int row = j >> 4;                // 0..127
            int dg  = j & 15;                // 0..15
            float4 v = *(const float4*)&x[((size_t)(r0 + row) * F_ + f) * 64 + dg * 4];
            xs[(dg * 4 + 0) * XS_STRIDE + row] = v.x;
            xs[(dg * 4 + 1) * XS_STRIDE + row] = v.y;
            xs[(dg * 4 + 2) * XS_STRIDE + row] = v.z;
            xs[(dg * 4 + 3) * XS_STRIDE + row] = v.w;
        }
        __syncthreads();

        const float maskv = g_mask_buf[gr * 32 + f];

        // ---- stage 1: hh1 = elu(x @ w1 + b1) ----
        {
            float acc[64];
#pragma unroll
            for (int e = 0; e < 64; e++) acc[e] = b1s[e];
#pragma unroll 4
            for (int d = 0; d < 64; d++) {
                float xv = xs[d * XS_STRIDE + r];
#pragma unroll
                for (int e = 0; e < 64; e++) acc[e] = fmaf(xv, w1s[d * 64 + e], acc[e]);
            }
#pragma unroll
            for (int e = 0; e < 64; e++) {
                float v = acc[e];
                hhs[e * XS_STRIDE + r] = v > 0.f ? v : expm1f(v);
            }
        }
        // ---- stage 2: hh2 = hh1 @ w2 + b2 ----
        {
            float acc[64];
#pragma unroll
            for (int e = 0; e < 64; e++) acc[e] = b2s[e];
#pragma unroll 4
            for (int d = 0; d < 64; d++) {
                float hv = hhs[d * XS_STRIDE + r];
#pragma unroll
                for (int e = 0; e < 64; e++) acc[e] = fmaf(hv, w2s[d * 64 + e], acc[e]);
            }
#pragma unroll
            for (int e = 0; e < 64; e++) hhs[e * XS_STRIDE + r] = acc[e];
        }
        // ---- stages 3+4: gate = sigmoid(hh2@gw+gb), lin = hh2@lw+lb ----
        float ga[64], la[64];
#pragma unroll
        for (int e = 0; e < 64; e++) { ga[e] = gbs[e]; la[e] = lbs[e]; }
#pragma unroll 2
        for (int d = 0; d < 64; d++) {
            float hv = hhs[d * XS_STRIDE + r];
#pragma unroll
            for (int e = 0; e < 64; e++) {
                ga[e] = fmaf(hv, gws[d * 64 + e], ga[e]);
                la[e] = fmaf(hv, lws[d * 64 + e], la[e]);
            }
        }
        // ---- y = sigmoid(ga)*la + x ; layernorm ; accumulate mask*vecs ----
        float s1 = 0.f, s2 = 0.f;
#pragma unroll
        for (int e = 0; e < 64; e++) {
            float sig = 1.f / (1.f + expf(-ga[e]));
            float yv  = fmaf(sig, la[e], xs[e * XS_STRIDE + r]);
            hhs[e * XS_STRIDE + r] = yv;   // reuse as y scratch (own column)
            s1 += yv;
            s2 = fmaf(yv, yv, s2);
        }
        float mean = s1 * (1.f / 64.f);
        float var  = fmaf(-mean, mean, s2 * (1.f / 64.f));
        float inv  = rsqrtf(var + EPS_);
#pragma unroll
        for (int e = 0; e < 64; e++) {
            float nv = fmaf((hhs[e * XS_STRIDE + r] - mean) * inv, gms[e], bts[e]);
            accs[e * XS_STRIDE + r] += maskv * nv;
        }
    }

    // ---- coalesced output: out[r0+row, 0:64] ----
    __syncthreads();
#pragma unroll
    for (int q = 0; q < 16; q++) {
        int j   = tid + K2_THREADS * q;  // float4 index 0..2047
        int row = j >> 4;
        int dg  = j & 15;
        float4 v;
        v.x = accs[(dg * 4 + 0) * XS_STRIDE + row];
        v.y = accs[(dg * 4 + 1) * XS_STRIDE + row];
        v.z = accs[(dg * 4 + 2) * XS_STRIDE + row];
        v.w = accs[(dg * 4 + 3) * XS_STRIDE + row];
        *(float4*)&out[(size_t)(r0 + row) * 64 + dg * 4] = v;
    }
}

// ===========================================================================
// Launcher
// ===========================================================================
extern "C" void kernel_launch(void* const* d_in, const int* in_sizes, int n_in,
                              void* d_out, int out_size)
{
    const float* x      = (const float*)d_in[0];
    const float* mw1    = (const float*)d_in[1];
    const float* mb1    = (const float*)d_in[2];
    const float* mw2    = (const float*)d_in[3];
    const float* mb2    = (const float*)d_in[4];
    const float* mlw    = (const float*)d_in[5];
    const float* mlb    = (const float*)d_in[6];
    const float* mgw    = (const float*)d_in[7];
    const float* mgb    = (const float*)d_in[8];
    const float* mlw2   = (const float*)d_in[9];
    const float* mlb2   = (const float*)d_in[10];
    const float* mgamma = (const float*)d_in[11];
    const float* mbeta  = (const float*)d_in[12];
    const float* w1     = (const float*)d_in[13];
    const float* b1     = (const float*)d_in[14];
    const float* w2     = (const float*)d_in[15];
    const float* b2     = (const float*)d_in[16];
    const float* gw     = (const float*)d_in[17];
    const float* gb     = (const float*)d_in[18];
    const float* lw     = (const float*)d_in[19];
    const float* lb     = (const float*)d_in[20];
    const float* gamma  = (const float*)d_in[21];
    const float* beta   = (const float*)d_in[22];

    float* out = (float*)d_out;
    // If the harness flattens both outputs (out[B,64] then mask[B,1,32]), write
    // the mask region too; otherwise skip it.
    float* out_mask = ((long long)out_size >= (long long)B_ * (64 + 32))
                          ? out + (size_t)B_ * 64 : nullptr;

    static const size_t k1_smem = K1_SMEM_FLOATS * sizeof(float);
    static const size_t k2_smem = K2_SMEM_FLOATS * sizeof(float);
    cudaFuncSetAttribute(k1_mask_kernel, cudaFuncAttributeMaxDynamicSharedMemorySize, (int)k1_smem);
    cudaFuncSetAttribute(k2_grn_kernel,  cudaFuncAttributeMaxDynamicSharedMemorySize, (int)k2_smem);

    float* gmask_ptr = nullptr;
    cudaGetSymbolAddress((void**)&gmask_ptr, g_mask_buf);

    k1_mask_kernel<<<B_ / BM, 256, k1_smem>>>(x, mw1, mb1, mw2, mb2, mlw, mlb,
                                              mgw, mgb, mlw2, mlb2, mgamma, mbeta,
                                              gmask_ptr, out_mask);
    k2_grn_kernel<<<B_ / K2_ROWS, K2_THREADS, k2_smem>>>(x, w1, b1, w2, b2,
                                                         gw, gb, lw, lb, gamma, beta,
                                                         out);
}

// round 2
// speedup vs baseline: 1.4568x; 1.4568x over previous
#include <cuda_runtime.h>
#include <cuda_bf16.h>
#include <math.h>

// Problem constants
#define B_  16384
#define F_  32
#define D_  64
#define IN_ 2048   // F_*D_
#define EPS_ 1e-5f

// ---------------------------------------------------------------------------
// Scratch (no device mallocs allowed):
//   g_mask_buf[B,F]   : mask from k1, consumed by k2
//   g_vbuf[F,B,64]    : mask-scaled normalized vectors from k2, reduced by k3
// ---------------------------------------------------------------------------
__device__ float g_mask_buf[(size_t)B_ * F_];
__device__ float g_vbuf[(size_t)F_ * B_ * D_];

// ===========================================================================
// Kernel 1: mask branch (unchanged from R1 — ~230us, 19% of total).
// ===========================================================================
#define BM 128
#define BN 96
#define BK 32
#define AS_STRIDE 36
#define BS_STRIDE 100
#define CS_STRIDE 97
#define K1_SMEM_FLOATS 24576

__global__ __launch_bounds__(256, 1)
void k1_mask_kernel(const float* __restrict__ x,
                    const float* __restrict__ mw1, const float* __restrict__ mb1,
                    const float* __restrict__ mw2, const float* __restrict__ mb2,
                    const float* __restrict__ mlw, const float* __restrict__ mlb,
                    const float* __restrict__ mgw, const float* __restrict__ mgb,
                    const float* __restrict__ mlw2, const float* __restrict__ mlb2,
                    const float* __restrict__ mgamma, const float* __restrict__ mbeta,
                    float* __restrict__ gmask, float* __restrict__ out_mask)
{
    extern __shared__ float sm[];
    float* As    = sm;
    float* Bs    = As  + BM * AS_STRIDE;
    float* Cs    = Bs  + BK * BS_STRIDE;
    float* mw2s  = Cs  + BM * CS_STRIDE;
    float* mgws  = mw2s + 64 * 32;
    float* mlw2s = mgws + 32 * 32;
    float* mb1s  = mlw2s + 32 * 32;
    float* mb2s  = mb1s + 64;
    float* mgbs  = mb2s + 32;
    float* mlb2s = mgbs + 32;
    float* mlbs  = mlb2s + 32;
    float* mgammas = mlbs + 32;
    float* mbetas  = mgammas + 32;

    const int tid = threadIdx.x;
    const int ty = tid / 16;
    const int tx = tid % 16;
    const int m0 = blockIdx.x * BM;

    for (int i = tid; i < 64 * 32; i += 256) mw2s[i] = mw2[i];
    for (int i = tid; i < 32 * 32; i += 256) { mgws[i] = mgw[i]; mlw2s[i] = mlw2[i]; }
    if (tid < 64) mb1s[tid] = mb1[tid];
    if (tid < 32) {
        mb2s[tid]  = mb2[tid];  mgbs[tid] = mgb[tid];  mlb2s[tid] = mlb2[tid];
        mlbs[tid]  = mlb[tid];  mgammas[tid] = mgamma[tid]; mbetas[tid] = mbeta[tid];
    }

    float c[8][6];
#pragma unroll
    for (int i = 0; i < 8; i++)
#pragma unroll
        for (int j = 0; j < 6; j++) c[i][j] = 0.f;

    const int ar  = tid / 8;
    const int ac  = (tid % 8) * 4;
    const int br  = tid / 8;
    const int bc8 = tid % 8;

    for (int k0 = 0; k0 < IN_; k0 += BK) {
        __syncthreads();
#pragma unroll
        for (int p = 0; p < 4; p++) {
            int m = ar + 32 * p;
            float4 v = *(const float4*)&x[(size_t)(m0 + m) * IN_ + k0 + ac];
            *(float4*)&As[m * AS_STRIDE + ac] = v;
        }
#pragma unroll
        for (int q = 0; q < 3; q++) {
            int c4  = bc8 * 3 + q;
            int col = c4 * 4;
            float4 v;
            if (col < 64) v = *(const float4*)&mw1[(size_t)(k0 + br) * 64 + col];
            else          v = *(const float4*)&mlw[(size_t)(k0 + br) * 32 + (col - 64)];
            *(float4*)&Bs[br * BS_STRIDE + col] = v;
        }
        __syncthreads();

#pragma unroll
        for (int k = 0; k < BK; k++) {
            float a[8], b[6];
#pragma unroll
            for (int i = 0; i < 8; i++) a[i] = As[(ty * 8 + i) * AS_STRIDE + k];
#pragma unroll
            for (int j = 0; j < 3; j++) {
                float2 bv = *(const float2*)&Bs[k * BS_STRIDE + tx * 6 + 2 * j];
                b[2 * j] = bv.x; b[2 * j + 1] = bv.y;
            }
#pragma unroll
            for (int i = 0; i < 8; i++)
#pragma unroll
                for (int j = 0; j < 6; j++) c[i][j] = fmaf(a[i], b[j], c[i][j]);
        }
    }
    __syncthreads();
#pragma unroll
    for (int i = 0; i < 8; i++)
#pragma unroll
        for (int j = 0; j < 6; j++)
            Cs[(ty * 8 + i) * CS_STRIDE + tx * 6 + j] = c[i][j];
    __syncthreads();

    if (tid < BM) {
        const int base = tid * CS_STRIDE;
        const size_t gr = (size_t)(m0 + tid);

#pragma unroll 4
        for (int e = 0; e < 64; e++) {
            float v = Cs[base + e] + mb1s[e];
            Cs[base + e] = v > 0.f ? v : expm1f(v);
        }
        float h[32];
#pragma unroll
        for (int j = 0; j < 32; j++) h[j] = mb2s[j];
#pragma unroll 4
        for (int e = 0; e < 64; e++) {
            float ev = Cs[base + e];
#pragma unroll
            for (int j = 0; j < 32; j++) h[j] = fmaf(ev, mw2s[e * 32 + j], h[j]);
        }
#pragma unroll
        for (int j = 0; j < 32; j++) Cs[base + j] = h[j];

        float g[32], l[32];
#pragma unroll
        for (int j = 0; j < 32; j++) { g[j] = mgbs[j]; l[j] = mlb2s[j]; }
#pragma unroll 2
        for (int i = 0; i < 32; i++) {
            float hv = Cs[base + i];
#pragma unroll
            for (int j = 0; j < 32; j++) {
                g[j] = fmaf(hv, mgws[i * 32 + j], g[j]);
                l[j] = fmaf(hv, mlw2s[i * 32 + j], l[j]);
            }
        }
        float pre[32];
#pragma unroll
        for (int j = 0; j < 32; j++) {
            float sig = 1.f / (1.f + expf(-g[j]));
            pre[j] = fmaf(sig, l[j], Cs[base + 64 + j] + mlbs[j]);
        }
        float mean = 0.f;
#pragma unroll
        for (int j = 0; j < 32; j++) mean += pre[j];
        mean *= (1.f / 32.f);
        float var = 0.f;
#pragma unroll
        for (int j = 0; j < 32; j++) { float d = pre[j] - mean; var = fmaf(d, d, var); }
        var *= (1.f / 32.f);
        float inv = rsqrtf(var + EPS_);
        float mx = -3.4e38f;
#pragma unroll
        for (int j = 0; j < 32; j++) {
            pre[j] = fmaf((pre[j] - mean) * inv, mgammas[j], mbetas[j]);
            mx = fmaxf(mx, pre[j]);
        }
        float ssum = 0.f;
#pragma unroll
        for (int j = 0; j < 32; j++) { pre[j] = expf(pre[j] - mx); ssum += pre[j]; }
        float rinv = 1.f / ssum;
#pragma unroll
        for (int j = 0; j < 32; j++) {
            float mv = pre[j] * rinv;
            gmask[gr * 32 + j] = mv;
            if (out_mask) out_mask[gr * 32 + j] = mv;
        }
    }
}

// ===========================================================================
// Kernel 2 (REWRITTEN): feature-per-CTA, register-blocked GEMM chain.
// grid = F * (B/128) = 4096 CTAs, 256 threads, 2 CTAs/SM target.
// Thread tile: 4 rows x 8 cols. Stages: elu(x@w1), @w2, sigmoid(@gw)*( @lw )
// + x, layernorm (shfl row-reduce), scale by mask, write to g_vbuf[f][b][d].
// Weight smem double-duty: {w1,w2} then re-staged {gw,lw}.
// ===========================================================================
#define R2   128
#define T2   256
#define XSTR 68   // row stride (floats) for xs/hhs: 16B-aligned rows, banks ok

// smem floats: w0 4096 + w1 4096 + xs 128*68 + hh 128*68 + bias 384 + mask 128
#define K2_SMEM_FLOATS (4096 + 4096 + R2*XSTR + R2*XSTR + 384 + 128)

__global__ __launch_bounds__(T2, 2)
void k2_grn_kernel(const float* __restrict__ x,
                   const float* __restrict__ w1, const float* __restrict__ b1,
                   const float* __restrict__ w2, const float* __restrict__ b2,
                   const float* __restrict__ gw, const float* __restrict__ gb,
                   const float* __restrict__ lw, const float* __restrict__ lb,
                   const float* __restrict__ gamma, const float* __restrict__ beta,
                   const float* __restrict__ gmask, float* __restrict__ vbuf)
{
    extern __shared__ float sm[];
    float* w0s  = sm;                 // 4096: w1, later gw
    float* w1s  = w0s + 4096;         // 4096: w2, later lw
    float* xs   = w1s + 4096;         // [128][XSTR]
    float* hhs  = xs  + R2 * XSTR;    // [128][XSTR]
    float* bias = hhs + R2 * XSTR;    // b1,b2,gb,lb,gamma,beta (64 each)
    float* msk  = bias + 384;         // 128

    const int tid = threadIdx.x;
    const int f   = blockIdx.x >> 7;        // feature
    const int rb  = blockIdx.x & 127;       // row block
    const int r0  = rb * R2;
    const size_t wo = (size_t)f * 4096;

    // ---- stage w1 -> w0s, w2 -> w1s; xs; biases; mask ----
#pragma unroll
    for (int q = 0; q < 4; q++) {
        int i4 = tid + T2 * q;
        ((float4*)w0s)[i4] = ((const float4*)(w1 + wo))[i4];
        ((float4*)w1s)[i4] = ((const float4*)(w2 + wo))[i4];
    }
#pragma unroll
    for (int q = 0; q < 8; q++) {
        int j   = tid + T2 * q;     // float4 units, 0..2047
        int row = j >> 4;
        int dg  = j & 15;
        float4 v = *(const float4*)&x[((size_t)(r0 + row) * F_ + f) * 64 + dg * 4];
        *(float4*)&xs[row * XSTR + dg * 4] = v;
    }
    if (tid < 64) {
        bias[tid]       = b1[f * 64 + tid];
        bias[64 + tid]  = b2[f * 64 + tid];
        bias[128 + tid] = gb[f * 64 + tid];
        bias[192 + tid] = lb[f * 64 + tid];
        bias[256 + tid] = gamma[f * 64 + tid];
        bias[320 + tid] = beta[f * 64 + tid];
    }
    if (tid < 128) msk[tid] = gmask[(size_t)(r0 + tid) * F_ + f];
    __syncthreads();

    const int ty = tid >> 3;       // 0..31
    const int tx = tid & 7;        // 0..7
    const int Rr = ty * 4;         // rows base (4 rows)
    const int Cc = tx * 8;         // cols base (8 cols)

    float acc[4][8];

    // ================= stage 1: hh1 = elu(x @ w1 + b1) =================
    {
        float4 bb0 = *(float4*)&bias[Cc], bb1 = *(float4*)&bias[Cc + 4];
#pragma unroll
        for (int i = 0; i < 4; i++) {
            acc[i][0]=bb0.x; acc[i][1]=bb0.y; acc[i][2]=bb0.z; acc[i][3]=bb0.w;
            acc[i][4]=bb1.x; acc[i][5]=bb1.y; acc[i][6]=bb1.z; acc[i][7]=bb1.w;
        }
        for (int d = 0; d < 64; d += 4) {
            float4 a4[4];
#pragma unroll
            for (int i = 0; i < 4; i++) a4[i] = *(float4*)&xs[(Rr + i) * XSTR + d];
#pragma unroll
            for (int dd = 0; dd < 4; dd++) {
                float4 wA = *(float4*)&w0s[(d + dd) * 64 + Cc];
                float4 wB = *(float4*)&w0s[(d + dd) * 64 + Cc + 4];
#pragma unroll
                for (int i = 0; i < 4; i++) {
                    float av = (dd == 0) ? a4[i].x : (dd == 1) ? a4[i].y : (dd == 2) ? a4[i].z : a4[i].w;
                    acc[i][0] = fmaf(av, wA.x, acc[i][0]);
                    acc[i][1] = fmaf(av, wA.y, acc[i][1]);
                    acc[i][2] = fmaf(av, wA.z, acc[i][2]);
                    acc[i][3] = fmaf(av, wA.w, acc[i][3]);
                    acc[i][4] = fmaf(av, wB.x, acc[i][4]);
                    acc[i][5] = fmaf(av, wB.y, acc[i][5]);
                    acc[i][6] = fmaf(av, wB.z, acc[i][6]);
                    acc[i][7] = fmaf(av, wB.w, acc[i][7]);
                }
            }
        }
#pragma unroll
        for (int i = 0; i < 4; i++)
#pragma unroll
            for (int j = 0; j < 8; j++) {
                float v = acc[i][j];
                acc[i][j] = v > 0.f ? v : (__expf(v) - 1.0f);
            }
        // write hh1 (region unused until now — no hazard before the sync)
#pragma unroll
        for (int i = 0; i < 4; i++) {
            *(float4*)&hhs[(Rr + i) * XSTR + Cc]     = make_float4(acc[i][0], acc[i][1], acc[i][2], acc[i][3]);
            *(float4*)&hhs[(Rr + i) * XSTR + Cc + 4] = make_float4(acc[i][4], acc[i][5], acc[i][6], acc[i][7]);
        }
    }
    __syncthreads();   // stage1 w0s reads done; hh1 visible

    // reload gw -> w0s (w0s free now); stage2 uses only w1s + hhs
#pragma unroll
    for (int q = 0; q < 4; q++) {
        int i4 = tid + T2 * q;
        ((float4*)w0s)[i4] = ((const float4*)(gw + wo))[i4];
    }

    // ================= stage 2: hh2 = hh1 @ w2 + b2 =================
    {
        float4 bb0 = *(float4*)&bias[64 + Cc], bb1 = *(float4*)&bias[64 + Cc + 4];
#pragma unroll
        for (int i = 0; i < 4; i++) {
            acc[i][0]=bb0.x; acc[i][1]=bb0.y; acc[i][2]=bb0.z; acc[i][3]=bb0.w;
            acc[i][4]=bb1.x; acc[i][5]=bb1.y; acc[i][6]=bb1.z; acc[i][7]=bb1.w;
        }
        for (int d = 0; d < 64; d += 4) {
            float4 a4[4];
#pragma unroll
            for (int i = 0; i < 4; i++) a4[i] = *(float4*)&hhs[(Rr + i) * XSTR + d];
#pragma unroll
            for (int dd = 0; dd < 4; dd++) {
                float4 wA = *(float4*)&w1s[(d + dd) * 64 + Cc];
                float4 wB = *(float4*)&w1s[(d + dd) * 64 + Cc + 4];
#pragma unroll
                for (int i = 0; i < 4; i++) {
                    float av = (dd == 0) ? a4[i].x : (dd == 1) ? a4[i].y : (dd == 2) ? a4[i].z : a4[i].w;
                    acc[i][0] = fmaf(av, wA.x, acc[i][0]);
                    acc[i][1] = fmaf(av, wA.y, acc[i][1]);
                    acc[i][2] = fmaf(av, wA.z, acc[i][2]);
                    acc[i][3] = fmaf(av, wA.w, acc[i][3]);
                    acc[i][4] = fmaf(av, wB.x, acc[i][4]);
                    acc[i][5] = fmaf(av, wB.y, acc[i][5]);
                    acc[i][6] = fmaf(av, wB.z, acc[i][6]);
                    acc[i][7] = fmaf(av, wB.w, acc[i][7]);
                }
            }
        }
    }
    __syncthreads();   // stage2 hhs + w1s reads done; gw staged

    // overwrite hhs with hh2; reload lw -> w1s
#pragma unroll
    for (int i = 0; i < 4; i++) {
        *(float4*)&hhs[(Rr + i) * XSTR + Cc]     = make_float4(acc[i][0], acc[i][1], acc[i][2], acc[i][3]);
        *(float4*)&hhs[(Rr + i) * XSTR + Cc + 4] = make_float4(acc[i][4], acc[i][5], acc[i][6], acc[i][7]);
    }
#pragma unroll
    for (int q = 0; q < 4; q++) {
        int i4 = tid + T2 * q;
        ((float4*)w1s)[i4] = ((const float4*)(lw + wo))[i4];
    }
    __syncthreads();   // hh2 + gw + lw visible

    // ============ stage 3+4: ga = hh2@gw+gb, la = hh2@lw+lb ============
    {
        float ga[4][8], la[4][8];
        {
            float4 g0 = *(float4*)&bias[128 + Cc], g1 = *(float4*)&bias[128 + Cc + 4];
            float4 l0 = *(float4*)&bias[192 + Cc], l1 = *(float4*)&bias[192 + Cc + 4];
#pragma unroll
            for (int i = 0; i < 4; i++) {
                ga[i][0]=g0.x; ga[i][1]=g0.y; ga[i][2]=g0.z; ga[i][3]=g0.w;
                ga[i][4]=g1.x; ga[i][5]=g1.y; ga[i][6]=g1.z; ga[i][7]=g1.w;
                la[i][0]=l0.x; la[i][1]=l0.y; la[i][2]=l0.z; la[i][3]=l0.w;
                la[i][4]=l1.x; la[i][5]=l1.y; la[i][6]=l1.z; la[i][7]=l1.w;
            }
        }
        for (int d = 0; d < 64; d += 4) {
            float4 a4[4];
#pragma unroll
            for (int i = 0; i < 4; i++) a4[i] = *(float4*)&hhs[(Rr + i) * XSTR + d];
#pragma unroll
            for (int dd = 0; dd < 4; dd++) {
                float4 gA = *(float4*)&w0s[(d + dd) * 64 + Cc];
                float4 gB = *(float4*)&w0s[(d + dd) * 64 + Cc + 4];
                float4 lA = *(float4*)&w1s[(d + dd) * 64 + Cc];
                float4 lB = *(float4*)&w1s[(d + dd) * 64 + Cc + 4];
#pragma unroll
                for (int i = 0; i < 4; i++) {
                    float av = (dd == 0) ? a4[i].x : (dd == 1) ? a4[i].y : (dd == 2) ? a4[i].z : a4[i].w;
                    ga[i][0] = fmaf(av, gA.x, ga[i][0]);
                    ga[i][1] = fmaf(av, gA.y, ga[i][1]);
                    ga[i][2] = fmaf(av, gA.z, ga[i][2]);
                    ga[i][3] = fmaf(av, gA.w, ga[i][3]);
                    ga[i][4] = fmaf(av, gB.x, ga[i][4]);
                    ga[i][5] = fmaf(av, gB.y, ga[i][5]);
                    ga[i][6] = fmaf(av, gB.z, ga[i][6]);
                    ga[i][7] = fmaf(av, gB.w, ga[i][7]);
                    la[i][0] = fmaf(av, lA.x, la[i][0]);
                    la[i][1] = fmaf(av, lA.y, la[i][1]);
                    la[i][2] = fmaf(av, lA.z, la[i][2]);
                    la[i][3] = fmaf(av, lA.w, la[i][3]);
                    la[i][4] = fmaf(av, lB.x, la[i][4]);
                    la[i][5] = fmaf(av, lB.y, la[i][5]);
                    la[i][6] = fmaf(av, lB.z, la[i][6]);
                    la[i][7] = fmaf(av, lB.w, la[i][7]);
                }
            }
        }

        // y = sigmoid(ga)*la + x; layernorm per row (reduce over tx lanes);
        // scale by mask; write to vbuf[f][r][d].
        float4 gm0 = *(float4*)&bias[256 + Cc], gm1 = *(float4*)&bias[256 + Cc + 4];
        float4 bt0 = *(float4*)&bias[320 + Cc], bt1 = *(float4*)&bias[320 + Cc + 4];
        float gmv[8] = {gm0.x,gm0.y,gm0.z,gm0.w,gm1.x,gm1.y,gm1.z,gm1.w};
        float btv[8] = {bt0.x,bt0.y,bt0.z,bt0.w,bt1.x,bt1.y,bt1.z,bt1.w};

#pragma unroll
        for (int i = 0; i < 4; i++) {
            float yv[8];
            float s1 = 0.f, s2 = 0.f;
            float4 x0 = *(float4*)&xs[(Rr + i) * XSTR + Cc];
            float4 x1 = *(float4*)&xs[(Rr + i) * XSTR + Cc + 4];
            float xr[8] = {x0.x,x0.y,x0.z,x0.w,x1.x,x1.y,x1.z,x1.w};
#pragma unroll
            for (int j = 0; j < 8; j++) {
                float sig = 1.f / (1.f + __expf(-ga[i][j]));
                float v = fmaf(sig, la[i][j], xr[j]);
                yv[j] = v;
                s1 += v;
                s2 = fmaf(v, v, s2);
            }
            // sum across the 8 tx lanes (lane bits 0..2)
#pragma unroll
            for (int o = 1; o < 8; o <<= 1) {
                s1 += __shfl_xor_sync(0xFFFFFFFFu, s1, o);
                s2 += __shfl_xor_sync(0xFFFFFFFFu, s2, o);
            }
            float mean = s1 * (1.f / 64.f);
            float var  = fmaf(-mean, mean, s2 * (1.f / 64.f));
            float inv  = rsqrtf(var + EPS_);
            float mv   = msk[Rr + i];
            float o0[8];
#pragma unroll
            for (int j = 0; j < 8; j++)
                o0[j] = mv * fmaf((yv[j] - mean) * inv, gmv[j], btv[j]);
            float* dst = &vbuf[((size_t)f * B_ + (size_t)(r0 + Rr + i)) * 64 + Cc];
            *(float4*)dst       = make_float4(o0[0], o0[1], o0[2], o0[3]);
            *(float4*)(dst + 4) = make_float4(o0[4], o0[5], o0[6], o0[7]);
        }
    }
}

// ===========================================================================
// Kernel 3: out[b,d] = sum_f vbuf[f,b,d]. Pure bandwidth (~268MB).
// ===========================================================================
#define K3_T 256
__global__ __launch_bounds__(K3_T, 4)
void k3_reduce_kernel(const float* __restrict__ vbuf, float* __restrict__ out)
{
    const size_t i4 = (size_t)blockIdx.x * K3_T + threadIdx.x;  // float4 index
    const size_t stride4 = (size_t)B_ * D_ / 4;                 // 262144
    const float4* vb = (const float4*)vbuf;
    float4 a = vb[i4];
#pragma unroll 4
    for (int f = 1; f < F_; f++) {
        float4 v = vb[i4 + (size_t)f * stride4];
        a.x += v.x; a.y += v.y; a.z += v.z; a.w += v.w;
    }
    ((float4*)out)[i4] = a;
}

// ===========================================================================
// Launcher
// ===========================================================================
extern "C" void kernel_launch(void* const* d_in, const int* in_sizes, int n_in,
                              void* d_out, int out_size)
{
    const float* x      = (const float*)d_in[0];
    const float* mw1    = (const float*)d_in[1];
    const float* mb1    = (const float*)d_in[2];
    const float* mw2    = (const float*)d_in[3];
    const float* mb2    = (const float*)d_in[4];
    const float* mlw    = (const float*)d_in[5];
    const float* mlb    = (const float*)d_in[6];
    const float* mgw    = (const float*)d_in[7];
    const float* mgb    = (const float*)d_in[8];
    const float* mlw2   = (const float*)d_in[9];
    const float* mlb2   = (const float*)d_in[10];
    const float* mgamma = (const float*)d_in[11];
    const float* mbeta  = (const float*)d_in[12];
    const float* w1     = (const float*)d_in[13];
    const float* b1     = (const float*)d_in[14];
    const float* w2     = (const float*)d_in[15];
    const float* b2     = (const float*)d_in[16];
    const float* gw     = (const float*)d_in[17];
    const float* gb     = (const float*)d_in[18];
    const float* lw     = (const float*)d_in[19];
    const float* lb     = (const float*)d_in[20];
    const float* gamma  = (const float*)d_in[21];
    const float* beta   = (const float*)d_in[22];

    float* out = (float*)d_out;
    float* out_mask = ((long long)out_size >= (long long)B_ * (64 + 32))
                          ? out + (size_t)B_ * 64 : nullptr;

    static const size_t k1_smem = K1_SMEM_FLOATS * sizeof(float);
    static const size_t k2_smem = K2_SMEM_FLOATS * sizeof(float);
    cudaFuncSetAttribute(k1_mask_kernel, cudaFuncAttributeMaxDynamicSharedMemorySize, (int)k1_smem);
    cudaFuncSetAttribute(k2_grn_kernel,  cudaFuncAttributeMaxDynamicSharedMemorySize, (int)k2_smem);

    float* gmask_ptr = nullptr;
    float* vbuf_ptr  = nullptr;
    cudaGetSymbolAddress((void**)&gmask_ptr, g_mask_buf);
    cudaGetSymbolAddress((void**)&vbuf_ptr,  g_vbuf);

    k1_mask_kernel<<<B_ / BM, 256, k1_smem>>>(x, mw1, mb1, mw2, mb2, mlw, mlb,
                                              mgw, mgb, mlw2, mlb2, mgamma, mbeta,
                                              gmask_ptr, out_mask);
    k2_grn_kernel<<<F_ * (B_ / R2), T2, k2_smem>>>(x, w1, b1, w2, b2,
                                                   gw, gb, lw, lb, gamma, beta,
                                                   gmask_ptr, vbuf_ptr);
    k3_reduce_kernel<<<(B_ * D_ / 4) / K3_T, K3_T>>>(vbuf_ptr, out);
}